// round 5
// baseline (speedup 1.0000x reference)
#include <cuda_runtime.h>
#include <math.h>

// ---------------- problem dims ----------------
#define B_   128
#define S_   512
#define D_   256
#define H_   512
#define E_   256
#define V_   1002
#define T_   34
#define G3H  1536   // 3*H

// ---------------- device scratch (static, allowed) ----------------
__device__ float g_GI [100663296];        // 65536 * 1536
__device__ float g_Y0 [33554432];         // 65536 * 512
__device__ float g_TG [1114112];          // 4352 * 256
__device__ float g_Yd0[2228224];          // 4352 * 512
__device__ float g_Yd1[2228224];          // 4352 * 512
__device__ float g_hA [2 * 65536];        // enc L0 ping-pong (final h in slot 0)
__device__ float g_hB [2 * 65536];        // enc L1 ping-pong (final h in slot 0)
__device__ float g_hC [2 * 65536];        // dec L0 ping-pong
__device__ float g_hD [2 * 65536];        // dec L1 ping-pong
__device__ float g_pooled[65536];
__device__ float g_F1 [327680];
__device__ float g_F2 [131072];
__device__ float g_F3 [128256];
__device__ float g_rowloss[128];
__device__ int   g_ctr[8];                // 2 barrier counters per persistent launch

// ---------------- generic SGEMM: C[M,N] = A[M,K] @ W[N,K]^T + bias ----------------
__global__ __launch_bounds__(256) void sgemm_nt_bias(
    const float* __restrict__ A, const float* __restrict__ W,
    const float* __restrict__ bias, float* __restrict__ C,
    int M, int N, int K)
{
    __shared__ float sA[16][128];
    __shared__ float sB[16][128];

    const int tid = threadIdx.x;
    const int tx  = tid & 15;
    const int ty  = tid >> 4;
    const int m0  = blockIdx.y * 128;
    const int n0  = blockIdx.x * 128;
    const int lr  = tid >> 2;
    const int lk  = (tid & 3) * 4;

    float acc[8][8];
    #pragma unroll
    for (int i = 0; i < 8; i++)
        #pragma unroll
        for (int j = 0; j < 8; j++) acc[i][j] = 0.f;

    for (int k0 = 0; k0 < K; k0 += 16) {
        #pragma unroll
        for (int h = 0; h < 2; h++) {
            int r = lr + 64 * h;
            float4 v = *(const float4*)(A + (long)(m0 + r) * K + k0 + lk);
            sA[lk + 0][r] = v.x; sA[lk + 1][r] = v.y;
            sA[lk + 2][r] = v.z; sA[lk + 3][r] = v.w;
        }
        #pragma unroll
        for (int h = 0; h < 2; h++) {
            int r = lr + 64 * h;
            int n = n0 + r;
            float4 v = make_float4(0.f, 0.f, 0.f, 0.f);
            if (n < N) v = *(const float4*)(W + (long)n * K + k0 + lk);
            sB[lk + 0][r] = v.x; sB[lk + 1][r] = v.y;
            sB[lk + 2][r] = v.z; sB[lk + 3][r] = v.w;
        }
        __syncthreads();

        #pragma unroll
        for (int kk = 0; kk < 16; kk++) {
            float a[8], b[8];
            #pragma unroll
            for (int i = 0; i < 8; i++) a[i] = sA[kk][ty + 16 * i];
            #pragma unroll
            for (int j = 0; j < 8; j++) b[j] = sB[kk][tx + 16 * j];
            #pragma unroll
            for (int i = 0; i < 8; i++)
                #pragma unroll
                for (int j = 0; j < 8; j++)
                    acc[i][j] = fmaf(a[i], b[j], acc[i][j]);
        }
        __syncthreads();
    }

    #pragma unroll
    for (int j = 0; j < 8; j++) {
        int n = n0 + tx + 16 * j;
        if (n >= N) continue;
        float bv = bias[n];
        #pragma unroll
        for (int i = 0; i < 8; i++) {
            int m = m0 + ty + 16 * i;
            C[(long)m * N + n] = acc[i][j] + bv;
        }
    }
}

// ---------------- persistent GRU layer ----------------
// grid = 128 CTAs (co-resident, 1/SM), 256 threads.
// CTA: colBase = (bid&63)*8 (8 h-cols, 24 gh-cols), rowBase = (bid>>6)*64.
// Whh slice (24x512) resident in smem for all steps. 4-way K-split across
// thread groups; software grid barrier per step within each row group (64 CTAs).
// Smem: sW 24*516 + sA 4*64*33 + gh 4*64*25 floats = 108928 B (dynamic).
#define SW_PAD 516
#define SMEM_PERSIST ((24 * SW_PAD + 4 * 64 * 33 + 4 * 64 * 25) * 4)

__global__ __launch_bounds__(256) void gru_layer_persist(
    const float* __restrict__ gi_base, long gi_bstride,     // gi(b,t) = gi_base + b*gi_bstride + t*G3H
    const float* __restrict__ Whh, const float* __restrict__ bhh,
    const float* __restrict__ h0,                           // [B,H] initial hidden
    float* __restrict__ hbuf,                               // [2][B*H] ping-pong
    float* __restrict__ y_out, long y_bstride, long y_tstride,
    int nsteps, int* counters)                              // counters[2], pre-zeroed
{
    extern __shared__ float smem[];
    float* sW = smem;                        // [24][SW_PAD]
    float* sA = smem + 24 * SW_PAD;          // [4][64][33]
    float* gh = sA + 4 * 64 * 33;            // [4][64][25]

    const int tid = threadIdx.x;
    const int bid = blockIdx.x;
    const int colBase  = (bid & 63) * 8;
    const int rowGroup = bid >> 6;
    const int rowBase  = rowGroup * 64;
    const int g  = tid >> 6;       // k-group 0..3 (128 k each)
    const int id = tid & 63;
    const int tr = id >> 2;        // 0..15 -> 4 rows each
    const int tc = id & 3;         // 0..3  -> 6 gh-cols each

    // ---- load resident Whh slice: 24 gh-rows x 512 k ----
    for (int i = tid; i < 24 * 128; i += 256) {
        int c  = i >> 7;
        int k4 = (i & 127) * 4;
        int j  = (c >> 3) * H_ + colBase + (c & 7);
        float4 v = *(const float4*)(Whh + (long)j * H_ + k4);
        float* d = sW + c * SW_PAD + k4;
        d[0] = v.x; d[1] = v.y; d[2] = v.z; d[3] = v.w;
    }
    __syncthreads();

    int* ctr = counters + rowGroup;
    float* sAg = sA + g * (64 * 33);
    const int kStart = g * 128;

    for (int t = 0; t < nsteps; t++) {
        const float* hp = (t == 0) ? h0 : (hbuf + (long)(t & 1) * 65536);
        float* ho = hbuf + (long)((t + 1) & 1) * 65536;
        const float* gi_t = gi_base + (long)t * G3H;

        float acc[4][6];
        #pragma unroll
        for (int i = 0; i < 4; i++)
            #pragma unroll
            for (int j = 0; j < 6; j++) acc[i][j] = 0.f;

        for (int kc = 0; kc < 128; kc += 32) {
            const int k0 = kStart + kc;
            // stage h tile (64 rows x 32 k) for this k-group; L2-only loads
            #pragma unroll
            for (int i2 = 0; i2 < 8; i2++) {
                int f = i2 * 64 + id;
                int r = f >> 3, k4 = (f & 7) * 4;
                float4 v = __ldcg((const float4*)(hp + (long)(rowBase + r) * H_ + k0 + k4));
                float* d = sAg + r * 33 + k4;
                d[0] = v.x; d[1] = v.y; d[2] = v.z; d[3] = v.w;
            }
            __syncthreads();

            const float* pa = sAg + (tr * 4) * 33;
            const float* pb = sW + (tc * 6) * SW_PAD + k0;
            #pragma unroll
            for (int k = 0; k < 32; k++) {
                float a[4], b[6];
                #pragma unroll
                for (int i = 0; i < 4; i++) a[i] = pa[i * 33 + k];
                #pragma unroll
                for (int j = 0; j < 6; j++) b[j] = pb[j * SW_PAD + k];
                #pragma unroll
                for (int i = 0; i < 4; i++)
                    #pragma unroll
                    for (int j = 0; j < 6; j++)
                        acc[i][j] = fmaf(a[i], b[j], acc[i][j]);
            }
            __syncthreads();
        }

        // write per-group partials
        #pragma unroll
        for (int i = 0; i < 4; i++)
            #pragma unroll
            for (int j = 0; j < 6; j++)
                gh[(g * 64 + tr * 4 + i) * 25 + tc * 6 + j] = acc[i][j];
        __syncthreads();

        // gate fusion: 64 rows x 8 h-cols = 512 outputs, 2 per thread
        #pragma unroll
        for (int q = 0; q < 2; q++) {
            int o   = q * 256 + tid;
            int row = o >> 3;
            int hc  = o & 7;
            int b   = rowBase + row;
            int col = colBase + hc;
            float ghr = 0.f, ghz = 0.f, ghn = 0.f;
            #pragma unroll
            for (int gg = 0; gg < 4; gg++) {
                const float* p = gh + (gg * 64 + row) * 25;
                ghr += p[hc]; ghz += p[8 + hc]; ghn += p[16 + hc];
            }
            ghr += bhh[col];
            ghz += bhh[H_ + col];
            ghn += bhh[2 * H_ + col];
            const float* gi = gi_t + (long)b * gi_bstride;
            float r  = 1.f / (1.f + expf(-(gi[col] + ghr)));
            float z  = 1.f / (1.f + expf(-(gi[H_ + col] + ghz)));
            float n  = tanhf(gi[2 * H_ + col] + r * ghn);
            float hpv = __ldcg(hp + (long)b * H_ + col);
            float hn = (1.f - z) * n + z * hpv;
            ho[(long)b * H_ + col] = hn;
            if (y_out)
                y_out[(long)b * y_bstride + (long)t * y_tstride + col] = hn;
        }

        // ---- grid barrier within row group (64 CTAs, all co-resident) ----
        __syncthreads();
        if (tid == 0) {
            __threadfence();
            atomicAdd(ctr, 1);
            int target = 64 * (t + 1);
            volatile int* vc = ctr;
            while (*vc < target) { __nanosleep(32); }
            __threadfence();
        }
        __syncthreads();
    }
}

// ---------------- embedding gather ----------------
__global__ void gather_emb(const int* __restrict__ ids, const float* __restrict__ emb,
                           float* __restrict__ tg)
{
    int m = blockIdx.x;
    int t = threadIdx.x;            // 64 threads, 1 float4 each
    int id = ids[m];
    const float4* src = (const float4*)(emb + (long)id * E_);
    float4* dst = (float4*)(tg + (long)m * E_);
    dst[t] = src[t];
}

// ---------------- masked time pooling ----------------
__global__ void pool_kernel(const float* __restrict__ y, const int* __restrict__ lengths,
                            float* __restrict__ pooled)
{
    int idx = blockIdx.x * blockDim.x + threadIdx.x;
    int b = idx >> 9, h = idx & 511;
    int L = lengths[b];
    float s = 0.f;
    for (int t = 0; t < L; t++) s += y[((long)b * T_ + t) * H_ + h];
    pooled[idx] = s;
}

// ---------------- per-row loss: lse(sigmoid(x)) - sigmoid(x)[END] ----------------
__global__ void rowloss_kernel(const float* __restrict__ x, float* __restrict__ rowloss)
{
    __shared__ float sh[V_];
    __shared__ float red[256];
    int b = blockIdx.x;
    int t = threadIdx.x;

    float mx = -1e30f;
    for (int v = t; v < V_; v += 256) {
        float s = 1.f / (1.f + expf(-x[(long)b * V_ + v]));
        sh[v] = s;
        mx = fmaxf(mx, s);
    }
    red[t] = mx; __syncthreads();
    for (int o = 128; o > 0; o >>= 1) {
        if (t < o) red[t] = fmaxf(red[t], red[t + o]);
        __syncthreads();
    }
    mx = red[0];
    __syncthreads();

    float sum = 0.f;
    for (int v = t; v < V_; v += 256) sum += expf(sh[v] - mx);
    red[t] = sum; __syncthreads();
    for (int o = 128; o > 0; o >>= 1) {
        if (t < o) red[t] += red[t + o];
        __syncthreads();
    }
    if (t == 0) rowloss[b] = (mx + logf(red[0])) - sh[V_ - 1];
}

__global__ void finalize_kernel(const float* __restrict__ rowloss, float* __restrict__ out)
{
    __shared__ float red[128];
    int t = threadIdx.x;
    red[t] = rowloss[t]; __syncthreads();
    for (int o = 64; o > 0; o >>= 1) {
        if (t < o) red[t] += red[t + o];
        __syncthreads();
    }
    if (t == 0) out[0] = red[0] / 128.f;
}

// ---------------- host ----------------
static void sgemm(const float* A, const float* Wt, const float* b, float* C,
                  int M, int N, int K)
{
    dim3 grid((N + 127) / 128, M / 128);
    sgemm_nt_bias<<<grid, 256>>>(A, Wt, b, C, M, N, K);
}

extern "C" void kernel_launch(void* const* d_in, const int* in_sizes, int n_in,
                              void* d_out, int out_size)
{
    const float* source    = (const float*)d_in[0];
    const int*   tgt_ids   = (const int*)  d_in[1];
    const int*   lengths   = (const int*)  d_in[2];
    const float* emb       = (const float*)d_in[3];
    const float* eWih0 = (const float*)d_in[4],  *eWhh0 = (const float*)d_in[5];
    const float* ebih0 = (const float*)d_in[6],  *ebhh0 = (const float*)d_in[7];
    const float* eWih1 = (const float*)d_in[8],  *eWhh1 = (const float*)d_in[9];
    const float* ebih1 = (const float*)d_in[10], *ebhh1 = (const float*)d_in[11];
    const float* dWih0 = (const float*)d_in[12], *dWhh0 = (const float*)d_in[13];
    const float* dbih0 = (const float*)d_in[14], *dbhh0 = (const float*)d_in[15];
    const float* dWih1 = (const float*)d_in[16], *dWhh1 = (const float*)d_in[17];
    const float* dbih1 = (const float*)d_in[18], *dbhh1 = (const float*)d_in[19];
    const float* fcW1 = (const float*)d_in[20], *fcb1 = (const float*)d_in[21];
    const float* fcW2 = (const float*)d_in[22], *fcb2 = (const float*)d_in[23];
    const float* fcW3 = (const float*)d_in[24], *fcb3 = (const float*)d_in[25];
    float* out = (float*)d_out;

    float *GI, *Y0, *TG, *Yd0, *Yd1, *hA, *hB, *hC, *hD, *pooled, *F1, *F2, *F3, *rl;
    int* ctr;
    cudaGetSymbolAddress((void**)&GI,  g_GI);
    cudaGetSymbolAddress((void**)&Y0,  g_Y0);
    cudaGetSymbolAddress((void**)&TG,  g_TG);
    cudaGetSymbolAddress((void**)&Yd0, g_Yd0);
    cudaGetSymbolAddress((void**)&Yd1, g_Yd1);
    cudaGetSymbolAddress((void**)&hA,  g_hA);
    cudaGetSymbolAddress((void**)&hB,  g_hB);
    cudaGetSymbolAddress((void**)&hC,  g_hC);
    cudaGetSymbolAddress((void**)&hD,  g_hD);
    cudaGetSymbolAddress((void**)&pooled, g_pooled);
    cudaGetSymbolAddress((void**)&F1,  g_F1);
    cudaGetSymbolAddress((void**)&F2,  g_F2);
    cudaGetSymbolAddress((void**)&F3,  g_F3);
    cudaGetSymbolAddress((void**)&rl,  g_rowloss);
    cudaGetSymbolAddress((void**)&ctr, g_ctr);

    cudaFuncSetAttribute(gru_layer_persist,
                         cudaFuncAttributeMaxDynamicSharedMemorySize, SMEM_PERSIST);

    // zero initial hidden states + all barrier counters
    cudaMemsetAsync(hA, 0, 65536 * sizeof(float), 0);
    cudaMemsetAsync(hB, 0, 65536 * sizeof(float), 0);
    cudaMemsetAsync(ctr, 0, 8 * sizeof(int), 0);

    // ---- encoder layer 0 ----
    sgemm(source, eWih0, ebih0, GI, B_ * S_, G3H, D_);
    gru_layer_persist<<<128, 256, SMEM_PERSIST>>>(
        GI, (long)S_ * G3H, eWhh0, ebhh0,
        hA /*h0=zeros*/, hA, Y0, (long)S_ * H_, (long)H_, S_, ctr + 0);

    // ---- encoder layer 1 ----
    sgemm(Y0, eWih1, ebih1, GI, B_ * S_, G3H, H_);
    gru_layer_persist<<<128, 256, SMEM_PERSIST>>>(
        GI, (long)S_ * G3H, eWhh1, ebhh1,
        hB /*h0=zeros*/, hB, (float*)0, 0, 0, S_, ctr + 2);

    // ---- decoder ----
    gather_emb<<<B_ * T_, 64>>>(tgt_ids, emb, TG);
    sgemm(TG, dWih0, dbih0, GI, B_ * T_, G3H, E_);
    gru_layer_persist<<<128, 256, SMEM_PERSIST>>>(
        GI, (long)T_ * G3H, dWhh0, dbhh0,
        hA /*enc L0 final (slot 0)*/, hC, Yd0, (long)T_ * H_, (long)H_, T_, ctr + 4);

    sgemm(Yd0, dWih1, dbih1, GI, B_ * T_, G3H, H_);
    gru_layer_persist<<<128, 256, SMEM_PERSIST>>>(
        GI, (long)T_ * G3H, dWhh1, dbhh1,
        hB /*enc L1 final (slot 0)*/, hD, Yd1, (long)T_ * H_, (long)H_, T_, ctr + 6);

    // ---- pool + FC head + loss ----
    pool_kernel<<<256, 256>>>(Yd1, lengths, pooled);
    sgemm(pooled, fcW1, fcb1, F1, B_, 5 * H_, H_);
    sgemm(F1,     fcW2, fcb2, F2, B_, 2 * H_, 5 * H_);
    sgemm(F2,     fcW3, fcb3, F3, B_, V_,     2 * H_);
    rowloss_kernel<<<B_, 256>>>(F3, rl);
    finalize_kernel<<<1, 128>>>(rl, out);
}

// round 7
// speedup vs baseline: 1.1603x; 1.1603x over previous
#include <cuda_runtime.h>
#include <cuda_bf16.h>
#include <math.h>
#include <stdint.h>

// ---------------- problem dims ----------------
#define B_   128
#define S_   512
#define D_   256
#define H_   512
#define E_   256
#define V_   1002
#define T_   34
#define G3H  1536   // 3*H

// ---------------- device scratch (static, allowed) ----------------
__device__ float g_GI [100663296];              // 65536 * 1536
__device__ float g_Y0 [33554432];               // 65536 * 512
__device__ float g_TG [1114112];                // 4352 * 256
__device__ float g_Yd0[2228224];                // 4352 * 512
__device__ float g_Yd1[2228224];                // 4352 * 512
__device__ float g_hA [2 * 65536];
__device__ float g_hB [2 * 65536];
__device__ float g_hC [2 * 65536];
__device__ float g_hD [2 * 65536];
__device__ float g_pooled[65536];
__device__ float g_F1 [327680];                 // 128 * 2560
__device__ float g_F2 [131072];                 // 128 * 1024
__device__ float g_F3 [131072];                 // 128 * 1024 (padded, Nreal=1002)
__device__ float g_rowloss[128];
__device__ int   g_ctr[8];
__device__ __nv_bfloat16 g_Acat[100663296];     // max 65536 * 1536 bf16
__device__ __nv_bfloat16 g_Wcat[8388608];       // max 2560 * 1536 / 1024*7680 bf16

// ================= fp32 -> (hi,lo,hi) / (hi,hi,lo) bf16 split converters =================
__global__ void conv_A(const float* __restrict__ A, __nv_bfloat16* __restrict__ Ac,
                       int K, long total)
{
    long idx = (long)blockIdx.x * 256 + threadIdx.x;
    if (idx >= total) return;
    int row = (int)(idx / K);
    int col = (int)(idx % K);
    float x = A[idx];
    __nv_bfloat16 hi = __float2bfloat16(x);
    __nv_bfloat16 lo = __float2bfloat16(x - __bfloat162float(hi));
    long base = (long)row * 3 * K;
    Ac[base + col]         = hi;
    Ac[base + K + col]     = lo;
    Ac[base + 2 * K + col] = hi;
}

__global__ void conv_W(const float* __restrict__ W, __nv_bfloat16* __restrict__ Wc,
                       int K, int Nreal, long total /* Npad*K */)
{
    long idx = (long)blockIdx.x * 256 + threadIdx.x;
    if (idx >= total) return;
    int n = (int)(idx / K);
    int c = (int)(idx % K);
    float x = (n < Nreal) ? W[(long)n * K + c] : 0.f;
    __nv_bfloat16 hi = __float2bfloat16(x);
    __nv_bfloat16 lo = __float2bfloat16(x - __bfloat162float(hi));
    long base = (long)n * 3 * K;
    Wc[base + c]         = hi;
    Wc[base + K + c]     = hi;
    Wc[base + 2 * K + c] = lo;
}

// ================= mma.sync bf16 GEMM: C = A[M,Kext] @ W[Npad,Kext]^T + bias =================
// CTA tile 128x128, 8 warps (4x2), warp tile 32x64. mma.m16n8k16 bf16 -> fp32.
// smem: double-buffered 64-wide K chunks, rows padded to 72 bf16 (conflict-free).
#define MMG_SAW   72                     // smem row stride in bf16 elems
#define MMG_TILE  (128 * MMG_SAW)        // elems per tile buffer
#define MMG_SMEM  (4 * MMG_TILE * 2)     // bytes: 2 bufs x (A+B) = 73728

__device__ __forceinline__ void mma16816(float* c, const uint32_t* a, const uint32_t* b)
{
    asm volatile(
        "mma.sync.aligned.m16n8k16.row.col.f32.bf16.bf16.f32 "
        "{%0,%1,%2,%3}, {%4,%5,%6,%7}, {%8,%9}, {%0,%1,%2,%3};"
        : "+f"(c[0]), "+f"(c[1]), "+f"(c[2]), "+f"(c[3])
        : "r"(a[0]), "r"(a[1]), "r"(a[2]), "r"(a[3]), "r"(b[0]), "r"(b[1]));
}

__global__ __launch_bounds__(256) void mma_gemm(
    const __nv_bfloat16* __restrict__ A, const __nv_bfloat16* __restrict__ Wc,
    const float* __restrict__ bias, float* __restrict__ C,
    int Kext, int Nreal, int ldC)
{
    extern __shared__ __nv_bfloat16 sm[];
    __nv_bfloat16* sA = sm;                     // [2][128][72]
    __nv_bfloat16* sB = sm + 2 * MMG_TILE;      // [2][128][72]

    const int tid  = threadIdx.x;
    const int wid  = tid >> 5;
    const int lane = tid & 31;
    const int g    = lane >> 2;                 // 0..7
    const int t    = lane & 3;                  // 0..3
    const int wm   = (wid & 3) * 32;            // warp M offset in tile
    const int wn   = (wid >> 2) * 64;           // warp N offset in tile
    const int m0   = blockIdx.y * 128;
    const int n0   = blockIdx.x * 128;

    // staging indices: 1024 uint4 per operand tile, 4 per thread
    const int sr = tid >> 1;                    // not used; keep simple mapping below

    float acc[2][8][4];
    #pragma unroll
    for (int i = 0; i < 2; i++)
        #pragma unroll
        for (int j = 0; j < 8; j++)
            #pragma unroll
            for (int q = 0; q < 4; q++) acc[i][j][q] = 0.f;

    const int nk = Kext >> 6;                   // 64-elem K chunks

    uint4 ra[4], rb[4];
    // prefetch chunk 0
    #pragma unroll
    for (int i = 0; i < 4; i++) {
        int f = i * 256 + tid;
        int r = f >> 3, u = f & 7;
        ra[i] = *(const uint4*)(A  + (long)(m0 + r) * Kext + u * 8);
        rb[i] = *(const uint4*)(Wc + (long)(n0 + r) * Kext + u * 8);
    }

    int p = 0;
    for (int kc = 0; kc < nk; kc++) {
        // store prefetched chunk into buffer p
        __nv_bfloat16* bufA = sA + p * MMG_TILE;
        __nv_bfloat16* bufB = sB + p * MMG_TILE;
        #pragma unroll
        for (int i = 0; i < 4; i++) {
            int f = i * 256 + tid;
            int r = f >> 3, u = f & 7;
            *(uint4*)(bufA + r * MMG_SAW + u * 8) = ra[i];
            *(uint4*)(bufB + r * MMG_SAW + u * 8) = rb[i];
        }
        __syncthreads();

        // prefetch next chunk
        if (kc + 1 < nk) {
            const int k0 = (kc + 1) << 6;
            #pragma unroll
            for (int i = 0; i < 4; i++) {
                int f = i * 256 + tid;
                int r = f >> 3, u = f & 7;
                ra[i] = *(const uint4*)(A  + (long)(m0 + r) * Kext + k0 + u * 8);
                rb[i] = *(const uint4*)(Wc + (long)(n0 + r) * Kext + k0 + u * 8);
            }
        }

        // compute 4 k16 steps from buffer p
        #pragma unroll
        for (int ks = 0; ks < 4; ks++) {
            const int kb = ks * 16 + 2 * t;
            uint32_t a[2][4], b[8][2];
            #pragma unroll
            for (int i = 0; i < 2; i++) {
                const __nv_bfloat16* base = bufA + (wm + i * 16) * MMG_SAW;
                a[i][0] = *(const uint32_t*)(base + (g    ) * MMG_SAW + kb);
                a[i][1] = *(const uint32_t*)(base + (g + 8) * MMG_SAW + kb);
                a[i][2] = *(const uint32_t*)(base + (g    ) * MMG_SAW + kb + 8);
                a[i][3] = *(const uint32_t*)(base + (g + 8) * MMG_SAW + kb + 8);
            }
            #pragma unroll
            for (int j = 0; j < 8; j++) {
                const __nv_bfloat16* base = bufB + (wn + j * 8 + g) * MMG_SAW;
                b[j][0] = *(const uint32_t*)(base + kb);
                b[j][1] = *(const uint32_t*)(base + kb + 8);
            }
            #pragma unroll
            for (int i = 0; i < 2; i++)
                #pragma unroll
                for (int j = 0; j < 8; j++)
                    mma16816(acc[i][j], a[i], b[j]);
        }
        __syncthreads();
        p ^= 1;
    }

    // epilogue: bias add + store (float2 per fragment row)
    #pragma unroll
    for (int i = 0; i < 2; i++) {
        #pragma unroll
        for (int j = 0; j < 8; j++) {
            int col = n0 + wn + j * 8 + 2 * t;
            if (col >= Nreal) continue;
            float b0 = bias[col], b1 = bias[col + 1];
            int row0 = m0 + wm + i * 16 + g;
            float2 v0 = make_float2(acc[i][j][0] + b0, acc[i][j][1] + b1);
            float2 v1 = make_float2(acc[i][j][2] + b0, acc[i][j][3] + b1);
            *(float2*)(C + (long)row0 * ldC + col)       = v0;
            *(float2*)(C + (long)(row0 + 8) * ldC + col) = v1;
        }
    }
    (void)sr;
}

// ================= persistent GRU layer (unchanged, proven) =================
#define SW_PAD 516
#define SMEM_PERSIST ((24 * SW_PAD + 4 * 64 * 33 + 4 * 64 * 25) * 4)

__global__ __launch_bounds__(256) void gru_layer_persist(
    const float* __restrict__ gi_base, long gi_bstride,
    const float* __restrict__ Whh, const float* __restrict__ bhh,
    const float* __restrict__ h0,
    float* __restrict__ hbuf,
    float* __restrict__ y_out, long y_bstride, long y_tstride,
    int nsteps, int* counters)
{
    extern __shared__ float smemf[];
    float* sW = smemf;
    float* sA = smemf + 24 * SW_PAD;
    float* gh = sA + 4 * 64 * 33;

    const int tid = threadIdx.x;
    const int bid = blockIdx.x;
    const int colBase  = (bid & 63) * 8;
    const int rowGroup = bid >> 6;
    const int rowBase  = rowGroup * 64;
    const int g  = tid >> 6;
    const int id = tid & 63;
    const int tr = id >> 2;
    const int tc = id & 3;

    for (int i = tid; i < 24 * 128; i += 256) {
        int c  = i >> 7;
        int k4 = (i & 127) * 4;
        int j  = (c >> 3) * H_ + colBase + (c & 7);
        float4 v = *(const float4*)(Whh + (long)j * H_ + k4);
        float* d = sW + c * SW_PAD + k4;
        d[0] = v.x; d[1] = v.y; d[2] = v.z; d[3] = v.w;
    }
    __syncthreads();

    int* ctr = counters + rowGroup;
    float* sAg = sA + g * (64 * 33);
    const int kStart = g * 128;

    for (int t = 0; t < nsteps; t++) {
        const float* hp = (t == 0) ? h0 : (hbuf + (long)(t & 1) * 65536);
        float* ho = hbuf + (long)((t + 1) & 1) * 65536;
        const float* gi_t = gi_base + (long)t * G3H;

        float acc[4][6];
        #pragma unroll
        for (int i = 0; i < 4; i++)
            #pragma unroll
            for (int j = 0; j < 6; j++) acc[i][j] = 0.f;

        for (int kc = 0; kc < 128; kc += 32) {
            const int k0 = kStart + kc;
            #pragma unroll
            for (int i2 = 0; i2 < 8; i2++) {
                int f = i2 * 64 + id;
                int r = f >> 3, k4 = (f & 7) * 4;
                float4 v = __ldcg((const float4*)(hp + (long)(rowBase + r) * H_ + k0 + k4));
                float* d = sAg + r * 33 + k4;
                d[0] = v.x; d[1] = v.y; d[2] = v.z; d[3] = v.w;
            }
            __syncthreads();

            const float* pa = sAg + (tr * 4) * 33;
            const float* pb = sW + (tc * 6) * SW_PAD + k0;
            #pragma unroll
            for (int k = 0; k < 32; k++) {
                float a[4], b[6];
                #pragma unroll
                for (int i = 0; i < 4; i++) a[i] = pa[i * 33 + k];
                #pragma unroll
                for (int j = 0; j < 6; j++) b[j] = pb[j * SW_PAD + k];
                #pragma unroll
                for (int i = 0; i < 4; i++)
                    #pragma unroll
                    for (int j = 0; j < 6; j++)
                        acc[i][j] = fmaf(a[i], b[j], acc[i][j]);
            }
            __syncthreads();
        }

        #pragma unroll
        for (int i = 0; i < 4; i++)
            #pragma unroll
            for (int j = 0; j < 6; j++)
                gh[(g * 64 + tr * 4 + i) * 25 + tc * 6 + j] = acc[i][j];
        __syncthreads();

        #pragma unroll
        for (int q = 0; q < 2; q++) {
            int o   = q * 256 + tid;
            int row = o >> 3;
            int hc  = o & 7;
            int b   = rowBase + row;
            int col = colBase + hc;
            float ghr = 0.f, ghz = 0.f, ghn = 0.f;
            #pragma unroll
            for (int gg = 0; gg < 4; gg++) {
                const float* p = gh + (gg * 64 + row) * 25;
                ghr += p[hc]; ghz += p[8 + hc]; ghn += p[16 + hc];
            }
            ghr += bhh[col];
            ghz += bhh[H_ + col];
            ghn += bhh[2 * H_ + col];
            const float* gi = gi_t + (long)b * gi_bstride;
            float r  = 1.f / (1.f + expf(-(gi[col] + ghr)));
            float z  = 1.f / (1.f + expf(-(gi[H_ + col] + ghz)));
            float n  = tanhf(gi[2 * H_ + col] + r * ghn);
            float hpv = __ldcg(hp + (long)b * H_ + col);
            float hn = (1.f - z) * n + z * hpv;
            ho[(long)b * H_ + col] = hn;
            if (y_out)
                y_out[(long)b * y_bstride + (long)t * y_tstride + col] = hn;
        }

        __syncthreads();
        if (tid == 0) {
            __threadfence();
            atomicAdd(ctr, 1);
            int target = 64 * (t + 1);
            volatile int* vc = ctr;
            while (*vc < target) { __nanosleep(32); }
            __threadfence();
        }
        __syncthreads();
    }
}

// ================= small kernels =================
__global__ void gather_emb(const int* __restrict__ ids, const float* __restrict__ emb,
                           float* __restrict__ tg)
{
    int m = blockIdx.x;
    int t = threadIdx.x;
    int id = ids[m];
    const float4* src = (const float4*)(emb + (long)id * E_);
    float4* dst = (float4*)(tg + (long)m * E_);
    dst[t] = src[t];
}

__global__ void pool_kernel(const float* __restrict__ y, const int* __restrict__ lengths,
                            float* __restrict__ pooled)
{
    int idx = blockIdx.x * blockDim.x + threadIdx.x;
    int b = idx >> 9, h = idx & 511;
    int L = lengths[b];
    float s = 0.f;
    for (int t = 0; t < L; t++) s += y[((long)b * T_ + t) * H_ + h];
    pooled[idx] = s;
}

__global__ void rowloss_kernel(const float* __restrict__ x, float* __restrict__ rowloss,
                               int ld)
{
    __shared__ float sh[V_];
    __shared__ float red[256];
    int b = blockIdx.x;
    int t = threadIdx.x;

    float mx = -1e30f;
    for (int v = t; v < V_; v += 256) {
        float s = 1.f / (1.f + expf(-x[(long)b * ld + v]));
        sh[v] = s;
        mx = fmaxf(mx, s);
    }
    red[t] = mx; __syncthreads();
    for (int o = 128; o > 0; o >>= 1) {
        if (t < o) red[t] = fmaxf(red[t], red[t + o]);
        __syncthreads();
    }
    mx = red[0];
    __syncthreads();

    float sum = 0.f;
    for (int v = t; v < V_; v += 256) sum += expf(sh[v] - mx);
    red[t] = sum; __syncthreads();
    for (int o = 128; o > 0; o >>= 1) {
        if (t < o) red[t] += red[t + o];
        __syncthreads();
    }
    if (t == 0) rowloss[b] = (mx + logf(red[0])) - sh[V_ - 1];
}

__global__ void finalize_kernel(const float* __restrict__ rowloss, float* __restrict__ out)
{
    __shared__ float red[128];
    int t = threadIdx.x;
    red[t] = rowloss[t]; __syncthreads();
    for (int o = 64; o > 0; o >>= 1) {
        if (t < o) red[t] += red[t + o];
        __syncthreads();
    }
    if (t == 0) out[0] = red[0] / 128.f;
}

// ================= host =================
static __nv_bfloat16 *s_Acat, *s_Wcat;

static void gemm_tc(const float* A, const float* W, const float* bias, float* C,
                    int M, int Nreal, int Npad, int K, int ldC)
{
    long ta = (long)M * K;
    conv_A<<<(unsigned)((ta + 255) / 256), 256>>>(A, s_Acat, K, ta);
    long tw = (long)Npad * K;
    conv_W<<<(unsigned)((tw + 255) / 256), 256>>>(W, s_Wcat, K, Nreal, tw);
    dim3 grid(Npad / 128, M / 128);
    mma_gemm<<<grid, 256, MMG_SMEM>>>(s_Acat, s_Wcat, bias, C, 3 * K, Nreal, ldC);
}

extern "C" void kernel_launch(void* const* d_in, const int* in_sizes, int n_in,
                              void* d_out, int out_size)
{
    const float* source    = (const float*)d_in[0];
    const int*   tgt_ids   = (const int*)  d_in[1];
    const int*   lengths   = (const int*)  d_in[2];
    const float* emb       = (const float*)d_in[3];
    const float* eWih0 = (const float*)d_in[4],  *eWhh0 = (const float*)d_in[5];
    const float* ebih0 = (const float*)d_in[6],  *ebhh0 = (const float*)d_in[7];
    const float* eWih1 = (const float*)d_in[8],  *eWhh1 = (const float*)d_in[9];
    const float* ebih1 = (const float*)d_in[10], *ebhh1 = (const float*)d_in[11];
    const float* dWih0 = (const float*)d_in[12], *dWhh0 = (const float*)d_in[13];
    const float* dbih0 = (const float*)d_in[14], *dbhh0 = (const float*)d_in[15];
    const float* dWih1 = (const float*)d_in[16], *dWhh1 = (const float*)d_in[17];
    const float* dbih1 = (const float*)d_in[18], *dbhh1 = (const float*)d_in[19];
    const float* fcW1 = (const float*)d_in[20], *fcb1 = (const float*)d_in[21];
    const float* fcW2 = (const float*)d_in[22], *fcb2 = (const float*)d_in[23];
    const float* fcW3 = (const float*)d_in[24], *fcb3 = (const float*)d_in[25];
    float* out = (float*)d_out;

    float *GI, *Y0, *TG, *Yd0, *Yd1, *hA, *hB, *hC, *hD, *pooled, *F1, *F2, *F3, *rl;
    int* ctr;
    cudaGetSymbolAddress((void**)&GI,  g_GI);
    cudaGetSymbolAddress((void**)&Y0,  g_Y0);
    cudaGetSymbolAddress((void**)&TG,  g_TG);
    cudaGetSymbolAddress((void**)&Yd0, g_Yd0);
    cudaGetSymbolAddress((void**)&Yd1, g_Yd1);
    cudaGetSymbolAddress((void**)&hA,  g_hA);
    cudaGetSymbolAddress((void**)&hB,  g_hB);
    cudaGetSymbolAddress((void**)&hC,  g_hC);
    cudaGetSymbolAddress((void**)&hD,  g_hD);
    cudaGetSymbolAddress((void**)&pooled, g_pooled);
    cudaGetSymbolAddress((void**)&F1,  g_F1);
    cudaGetSymbolAddress((void**)&F2,  g_F2);
    cudaGetSymbolAddress((void**)&F3,  g_F3);
    cudaGetSymbolAddress((void**)&rl,  g_rowloss);
    cudaGetSymbolAddress((void**)&ctr, g_ctr);
    cudaGetSymbolAddress((void**)&s_Acat, g_Acat);
    cudaGetSymbolAddress((void**)&s_Wcat, g_Wcat);

    cudaFuncSetAttribute(gru_layer_persist,
                         cudaFuncAttributeMaxDynamicSharedMemorySize, SMEM_PERSIST);
    cudaFuncSetAttribute(mma_gemm,
                         cudaFuncAttributeMaxDynamicSharedMemorySize, MMG_SMEM);

    cudaMemsetAsync(hA, 0, 65536 * sizeof(float), 0);
    cudaMemsetAsync(hB, 0, 65536 * sizeof(float), 0);
    cudaMemsetAsync(ctr, 0, 8 * sizeof(int), 0);

    // ---- encoder layer 0 ----
    gemm_tc(source, eWih0, ebih0, GI, B_ * S_, G3H, G3H, D_, G3H);
    gru_layer_persist<<<128, 256, SMEM_PERSIST>>>(
        GI, (long)S_ * G3H, eWhh0, ebhh0,
        hA, hA, Y0, (long)S_ * H_, (long)H_, S_, ctr + 0);

    // ---- encoder layer 1 ----
    gemm_tc(Y0, eWih1, ebih1, GI, B_ * S_, G3H, G3H, H_, G3H);
    gru_layer_persist<<<128, 256, SMEM_PERSIST>>>(
        GI, (long)S_ * G3H, eWhh1, ebhh1,
        hB, hB, (float*)0, 0, 0, S_, ctr + 2);

    // ---- decoder ----
    gather_emb<<<B_ * T_, 64>>>(tgt_ids, emb, TG);
    gemm_tc(TG, dWih0, dbih0, GI, B_ * T_, G3H, G3H, E_, G3H);
    gru_layer_persist<<<128, 256, SMEM_PERSIST>>>(
        GI, (long)T_ * G3H, dWhh0, dbhh0,
        hA, hC, Yd0, (long)T_ * H_, (long)H_, T_, ctr + 4);

    gemm_tc(Yd0, dWih1, dbih1, GI, B_ * T_, G3H, G3H, H_, G3H);
    gru_layer_persist<<<128, 256, SMEM_PERSIST>>>(
        GI, (long)T_ * G3H, dWhh1, dbhh1,
        hB, hD, Yd1, (long)T_ * H_, (long)H_, T_, ctr + 6);

    // ---- pool + FC head + loss ----
    pool_kernel<<<256, 256>>>(Yd1, lengths, pooled);
    gemm_tc(pooled, fcW1, fcb1, F1, B_, 5 * H_, 5 * H_, H_,     5 * H_);   // 128x2560
    gemm_tc(F1,     fcW2, fcb2, F2, B_, 2 * H_, 2 * H_, 5 * H_, 2 * H_);   // 128x1024
    gemm_tc(F2,     fcW3, fcb3, F3, B_, V_,     1024,   2 * H_, 1024);     // 128x1002 (pad 1024)
    rowloss_kernel<<<B_, 256>>>(F3, rl, 1024);
    finalize_kernel<<<1, 128>>>(rl, out);
}

// round 8
// speedup vs baseline: 1.1910x; 1.0265x over previous
#include <cuda_runtime.h>
#include <cuda_bf16.h>
#include <math.h>
#include <stdint.h>

// ---------------- problem dims ----------------
#define B_   128
#define S_   512
#define D_   256
#define H_   512
#define E_   256
#define V_   1002
#define T_   34
#define G3H  1536   // 3*H

// ---------------- device scratch (static, allowed) ----------------
__device__ float g_GI [100663296];              // 65536 * 1536
__device__ float g_Yd1[2228224];                // 4352 * 512 (fp32, for pooling)
__device__ float g_hA [2 * 65536];
__device__ float g_hB [2 * 65536];
__device__ float g_hC [2 * 65536];
__device__ float g_hD [2 * 65536];
__device__ float g_pooled[65536];
__device__ float g_F1 [327680];                 // 128 * 2560
__device__ float g_F2 [131072];                 // 128 * 1024
__device__ float g_F3 [131072];                 // 128 * 1024 (padded, Nreal=1002)
__device__ float g_rowloss[128];
__device__ int   g_ctr[8];
__device__ __nv_bfloat16 g_Acat[100663296];     // A in (hi|lo|hi) cat form
__device__ __nv_bfloat16 g_Wcat[8388608];       // W in (hi|hi|lo) cat form

// ================= fp32 -> bf16 split converters =================
__global__ void conv_A(const float* __restrict__ A, __nv_bfloat16* __restrict__ Ac,
                       int K, long total)
{
    long idx = (long)blockIdx.x * 256 + threadIdx.x;
    if (idx >= total) return;
    int row = (int)(idx / K);
    int col = (int)(idx % K);
    float x = A[idx];
    __nv_bfloat16 hi = __float2bfloat16(x);
    __nv_bfloat16 lo = __float2bfloat16(x - __bfloat162float(hi));
    long base = (long)row * 3 * K;
    Ac[base + col]         = hi;
    Ac[base + K + col]     = lo;
    Ac[base + 2 * K + col] = hi;
}

__global__ void conv_W(const float* __restrict__ W, __nv_bfloat16* __restrict__ Wc,
                       int K, int Nreal, long total /* Npad*K */)
{
    long idx = (long)blockIdx.x * 256 + threadIdx.x;
    if (idx >= total) return;
    int n = (int)(idx / K);
    int c = (int)(idx % K);
    float x = (n < Nreal) ? W[(long)n * K + c] : 0.f;
    __nv_bfloat16 hi = __float2bfloat16(x);
    __nv_bfloat16 lo = __float2bfloat16(x - __bfloat162float(hi));
    long base = (long)n * 3 * K;
    Wc[base + c]         = hi;
    Wc[base + K + c]     = hi;
    Wc[base + 2 * K + c] = lo;
}

// ================= mma.sync bf16 GEMM (ldmatrix + cp.async, 3 stages) =================
// CTA tile 128x128, 8 warps (4x2), warp tile 32x64. K chunk 64 bf16.
#define STAGES    3
#define MMG_SAW   72                            // padded row stride (bf16 elems)
#define MMG_TILE  (128 * MMG_SAW)               // elems per operand per stage
#define MMG_SMEM  (STAGES * 2 * MMG_TILE * 2)   // 110592 bytes

__device__ __forceinline__ void mma16816(float* c, const uint32_t* a, const uint32_t* b)
{
    asm volatile(
        "mma.sync.aligned.m16n8k16.row.col.f32.bf16.bf16.f32 "
        "{%0,%1,%2,%3}, {%4,%5,%6,%7}, {%8,%9}, {%0,%1,%2,%3};"
        : "+f"(c[0]), "+f"(c[1]), "+f"(c[2]), "+f"(c[3])
        : "r"(a[0]), "r"(a[1]), "r"(a[2]), "r"(a[3]), "r"(b[0]), "r"(b[1]));
}

__device__ __forceinline__ void ldmx4(uint32_t* r, uint32_t addr)
{
    asm volatile("ldmatrix.sync.aligned.m8n8.x4.shared.b16 {%0,%1,%2,%3}, [%4];"
        : "=r"(r[0]), "=r"(r[1]), "=r"(r[2]), "=r"(r[3]) : "r"(addr));
}

__device__ __forceinline__ void cp16(uint32_t dst, const void* src)
{
    asm volatile("cp.async.cg.shared.global [%0], [%1], 16;" :: "r"(dst), "l"(src));
}
#define CP_COMMIT() asm volatile("cp.async.commit_group;" ::: "memory")
#define CP_WAIT2()  asm volatile("cp.async.wait_group 2;" ::: "memory")

__device__ __forceinline__ uint32_t smem_u32(const void* p) {
    uint32_t a;
    asm("{ .reg .u64 t; cvta.to.shared.u64 t, %1; cvt.u32.u64 %0, t; }" : "=r"(a) : "l"(p));
    return a;
}

__global__ __launch_bounds__(256) void mma_gemm(
    const __nv_bfloat16* __restrict__ A, const __nv_bfloat16* __restrict__ Wc,
    const float* __restrict__ bias, float* __restrict__ C,
    int Kext, int Nreal, int ldC)
{
    extern __shared__ __nv_bfloat16 sm[];
    const uint32_t suA = smem_u32(sm);
    const uint32_t suB = suA + STAGES * MMG_TILE * 2;

    const int tid  = threadIdx.x;
    const int wid  = tid >> 5;
    const int lane = tid & 31;
    const int g    = lane >> 2;
    const int t    = lane & 3;
    const int wm   = (wid & 3) * 32;
    const int wn   = (wid >> 2) * 64;
    const int m0   = blockIdx.y * 128;
    const int n0   = blockIdx.x * 128;

    const int aoff = (wm + (lane & 15)) * MMG_SAW + (lane >> 4) * 8;
    const int boff = (wn + (lane & 15)) * MMG_SAW + (lane >> 4) * 8;

    float acc[2][8][4];
    #pragma unroll
    for (int i = 0; i < 2; i++)
        #pragma unroll
        for (int j = 0; j < 8; j++)
            #pragma unroll
            for (int q = 0; q < 4; q++) acc[i][j][q] = 0.f;

    const int nk = Kext >> 6;

    // prologue: stages 0..STAGES-2
    #pragma unroll
    for (int s = 0; s < STAGES - 1; s++) {
        if (s < nk) {
            const int k0 = s << 6;
            const uint32_t dA = suA + s * (MMG_TILE * 2);
            const uint32_t dB = suB + s * (MMG_TILE * 2);
            #pragma unroll
            for (int i = 0; i < 4; i++) {
                int f = i * 256 + tid;
                int r = f >> 3, u = (f & 7) * 8;
                cp16(dA + (uint32_t)(r * MMG_SAW + u) * 2, A  + (long)(m0 + r) * Kext + k0 + u);
                cp16(dB + (uint32_t)(r * MMG_SAW + u) * 2, Wc + (long)(n0 + r) * Kext + k0 + u);
            }
        }
        CP_COMMIT();
    }

    for (int kc = 0; kc < nk; kc++) {
        // issue stage kc+STAGES-1 (overwrites buffer computed at iter kc-1; safe after trailing sync)
        {
            const int kl = kc + STAGES - 1;
            if (kl < nk) {
                const int k0 = kl << 6;
                const int bfi = kl % STAGES;
                const uint32_t dA = suA + bfi * (MMG_TILE * 2);
                const uint32_t dB = suB + bfi * (MMG_TILE * 2);
                #pragma unroll
                for (int i = 0; i < 4; i++) {
                    int f = i * 256 + tid;
                    int r = f >> 3, u = (f & 7) * 8;
                    cp16(dA + (uint32_t)(r * MMG_SAW + u) * 2, A  + (long)(m0 + r) * Kext + k0 + u);
                    cp16(dB + (uint32_t)(r * MMG_SAW + u) * 2, Wc + (long)(n0 + r) * Kext + k0 + u);
                }
            }
            CP_COMMIT();
        }
        CP_WAIT2();            // group for stage kc complete
        __syncthreads();

        const int p = kc % STAGES;
        const uint32_t bA = suA + p * (MMG_TILE * 2);
        const uint32_t bB = suB + p * (MMG_TILE * 2);

        #pragma unroll
        for (int ks = 0; ks < 4; ks++) {
            uint32_t af[2][4], bf[4][4];
            #pragma unroll
            for (int i = 0; i < 2; i++)
                ldmx4(af[i], bA + 2u * (uint32_t)(aoff + i * 16 * MMG_SAW + ks * 16));
            #pragma unroll
            for (int j = 0; j < 4; j++)
                ldmx4(bf[j], bB + 2u * (uint32_t)(boff + j * 16 * MMG_SAW + ks * 16));
            #pragma unroll
            for (int i = 0; i < 2; i++)
                #pragma unroll
                for (int jj = 0; jj < 8; jj++) {
                    uint32_t b2[2] = { bf[jj >> 1][jj & 1], bf[jj >> 1][(jj & 1) + 2] };
                    mma16816(acc[i][jj], af[i], b2);
                }
        }
        __syncthreads();
    }

    // epilogue: bias add + store
    #pragma unroll
    for (int i = 0; i < 2; i++) {
        #pragma unroll
        for (int j = 0; j < 8; j++) {
            int col = n0 + wn + j * 8 + 2 * t;
            if (col >= Nreal) continue;
            float b0 = bias[col], b1 = bias[col + 1];
            int row0 = m0 + wm + i * 16 + g;
            float2 v0 = make_float2(acc[i][j][0] + b0, acc[i][j][1] + b1);
            float2 v1 = make_float2(acc[i][j][2] + b0, acc[i][j][3] + b1);
            *(float2*)(C + (long)row0 * ldC + col)       = v0;
            *(float2*)(C + (long)(row0 + 8) * ldC + col) = v1;
        }
    }
}

// ================= persistent GRU layer (R5-proven; + optional bf16-cat y output) =================
#define SW_PAD 516
#define SMEM_PERSIST ((24 * SW_PAD + 4 * 64 * 33 + 4 * 64 * 25) * 4)

__global__ __launch_bounds__(256) void gru_layer_persist(
    const float* __restrict__ gi_base, long gi_bstride,
    const float* __restrict__ Whh, const float* __restrict__ bhh,
    const float* __restrict__ h0,
    float* __restrict__ hbuf,
    float* __restrict__ y_out, long y_bstride, long y_tstride,
    __nv_bfloat16* __restrict__ ycat,          // optional (hi|lo|hi) rows of 3H, row = b*nsteps+t
    int nsteps, int* counters)
{
    extern __shared__ float smemf[];
    float* sW = smemf;
    float* sA = smemf + 24 * SW_PAD;
    float* gh = sA + 4 * 64 * 33;

    const int tid = threadIdx.x;
    const int bid = blockIdx.x;
    const int colBase  = (bid & 63) * 8;
    const int rowGroup = bid >> 6;
    const int rowBase  = rowGroup * 64;
    const int g  = tid >> 6;
    const int id = tid & 63;
    const int tr = id >> 2;
    const int tc = id & 3;

    for (int i = tid; i < 24 * 128; i += 256) {
        int c  = i >> 7;
        int k4 = (i & 127) * 4;
        int j  = (c >> 3) * H_ + colBase + (c & 7);
        float4 v = *(const float4*)(Whh + (long)j * H_ + k4);
        float* d = sW + c * SW_PAD + k4;
        d[0] = v.x; d[1] = v.y; d[2] = v.z; d[3] = v.w;
    }
    __syncthreads();

    int* ctr = counters + rowGroup;
    float* sAg = sA + g * (64 * 33);
    const int kStart = g * 128;

    for (int t = 0; t < nsteps; t++) {
        const float* hp = (t == 0) ? h0 : (hbuf + (long)(t & 1) * 65536);
        float* ho = hbuf + (long)((t + 1) & 1) * 65536;
        const float* gi_t = gi_base + (long)t * G3H;

        float acc[4][6];
        #pragma unroll
        for (int i = 0; i < 4; i++)
            #pragma unroll
            for (int j = 0; j < 6; j++) acc[i][j] = 0.f;

        for (int kc = 0; kc < 128; kc += 32) {
            const int k0 = kStart + kc;
            #pragma unroll
            for (int i2 = 0; i2 < 8; i2++) {
                int f = i2 * 64 + id;
                int r = f >> 3, k4 = (f & 7) * 4;
                float4 v = __ldcg((const float4*)(hp + (long)(rowBase + r) * H_ + k0 + k4));
                float* d = sAg + r * 33 + k4;
                d[0] = v.x; d[1] = v.y; d[2] = v.z; d[3] = v.w;
            }
            __syncthreads();

            const float* pa = sAg + (tr * 4) * 33;
            const float* pb = sW + (tc * 6) * SW_PAD + k0;
            #pragma unroll
            for (int k = 0; k < 32; k++) {
                float a[4], b[6];
                #pragma unroll
                for (int i = 0; i < 4; i++) a[i] = pa[i * 33 + k];
                #pragma unroll
                for (int j = 0; j < 6; j++) b[j] = pb[j * SW_PAD + k];
                #pragma unroll
                for (int i = 0; i < 4; i++)
                    #pragma unroll
                    for (int j = 0; j < 6; j++)
                        acc[i][j] = fmaf(a[i], b[j], acc[i][j]);
            }
            __syncthreads();
        }

        #pragma unroll
        for (int i = 0; i < 4; i++)
            #pragma unroll
            for (int j = 0; j < 6; j++)
                gh[(g * 64 + tr * 4 + i) * 25 + tc * 6 + j] = acc[i][j];
        __syncthreads();

        #pragma unroll
        for (int q = 0; q < 2; q++) {
            int o   = q * 256 + tid;
            int row = o >> 3;
            int hc  = o & 7;
            int b   = rowBase + row;
            int col = colBase + hc;
            float ghr = 0.f, ghz = 0.f, ghn = 0.f;
            #pragma unroll
            for (int gg = 0; gg < 4; gg++) {
                const float* p = gh + (gg * 64 + row) * 25;
                ghr += p[hc]; ghz += p[8 + hc]; ghn += p[16 + hc];
            }
            ghr += bhh[col];
            ghz += bhh[H_ + col];
            ghn += bhh[2 * H_ + col];
            const float* gi = gi_t + (long)b * gi_bstride;
            float r  = 1.f / (1.f + expf(-(gi[col] + ghr)));
            float z  = 1.f / (1.f + expf(-(gi[H_ + col] + ghz)));
            float n  = tanhf(gi[2 * H_ + col] + r * ghn);
            float hpv = __ldcg(hp + (long)b * H_ + col);
            float hn = (1.f - z) * n + z * hpv;
            ho[(long)b * H_ + col] = hn;
            if (y_out)
                y_out[(long)b * y_bstride + (long)t * y_tstride + col] = hn;
            if (ycat) {
                __nv_bfloat16 hi = __float2bfloat16(hn);
                __nv_bfloat16 lo = __float2bfloat16(hn - __bfloat162float(hi));
                __nv_bfloat16* yr = ycat + ((long)b * nsteps + t) * (3 * H_);
                yr[col]            = hi;
                yr[H_ + col]       = lo;
                yr[2 * H_ + col]   = hi;
            }
        }

        __syncthreads();
        if (tid == 0) {
            __threadfence();
            atomicAdd(ctr, 1);
            int target = 64 * (t + 1);
            volatile int* vc = ctr;
            while (*vc < target) { __nanosleep(32); }
            __threadfence();
        }
        __syncthreads();
    }
}

// ================= small kernels =================
__global__ void gather_emb_cat(const int* __restrict__ ids, const float* __restrict__ emb,
                               __nv_bfloat16* __restrict__ tg)
{
    int m = blockIdx.x;              // 0..4351
    int t = threadIdx.x;             // 256 threads, one elem each
    int id = ids[m];
    float x = emb[(long)id * E_ + t];
    __nv_bfloat16 hi = __float2bfloat16(x);
    __nv_bfloat16 lo = __float2bfloat16(x - __bfloat162float(hi));
    __nv_bfloat16* dst = tg + (long)m * (3 * E_);
    dst[t]            = hi;
    dst[E_ + t]       = lo;
    dst[2 * E_ + t]   = hi;
}

__global__ void pool_kernel(const float* __restrict__ y, const int* __restrict__ lengths,
                            float* __restrict__ pooled)
{
    int idx = blockIdx.x * blockDim.x + threadIdx.x;
    int b = idx >> 9, h = idx & 511;
    int L = lengths[b];
    float s = 0.f;
    for (int t = 0; t < L; t++) s += y[((long)b * T_ + t) * H_ + h];
    pooled[idx] = s;
}

__global__ void rowloss_kernel(const float* __restrict__ x, float* __restrict__ rowloss,
                               int ld)
{
    __shared__ float sh[V_];
    __shared__ float red[256];
    int b = blockIdx.x;
    int t = threadIdx.x;

    float mx = -1e30f;
    for (int v = t; v < V_; v += 256) {
        float s = 1.f / (1.f + expf(-x[(long)b * ld + v]));
        sh[v] = s;
        mx = fmaxf(mx, s);
    }
    red[t] = mx; __syncthreads();
    for (int o = 128; o > 0; o >>= 1) {
        if (t < o) red[t] = fmaxf(red[t], red[t + o]);
        __syncthreads();
    }
    mx = red[0];
    __syncthreads();

    float sum = 0.f;
    for (int v = t; v < V_; v += 256) sum += expf(sh[v] - mx);
    red[t] = sum; __syncthreads();
    for (int o = 128; o > 0; o >>= 1) {
        if (t < o) red[t] += red[t + o];
        __syncthreads();
    }
    if (t == 0) rowloss[b] = (mx + logf(red[0])) - sh[V_ - 1];
}

__global__ void finalize_kernel(const float* __restrict__ rowloss, float* __restrict__ out)
{
    __shared__ float red[128];
    int t = threadIdx.x;
    red[t] = rowloss[t]; __syncthreads();
    for (int o = 64; o > 0; o >>= 1) {
        if (t < o) red[t] += red[t + o];
        __syncthreads();
    }
    if (t == 0) out[0] = red[0] / 128.f;
}

// ================= host =================
static __nv_bfloat16 *s_Acat, *s_Wcat;

// full path: convert A fp32 -> cat, convert W, GEMM
static void gemm_full(const float* A, const float* W, const float* bias, float* C,
                      int M, int Nreal, int Npad, int K, int ldC)
{
    long ta = (long)M * K;
    conv_A<<<(unsigned)((ta + 255) / 256), 256>>>(A, s_Acat, K, ta);
    long tw = (long)Npad * K;
    conv_W<<<(unsigned)((tw + 255) / 256), 256>>>(W, s_Wcat, K, Nreal, tw);
    dim3 grid(Npad / 128, M / 128);
    mma_gemm<<<grid, 256, MMG_SMEM>>>(s_Acat, s_Wcat, bias, C, 3 * K, Nreal, ldC);
}

// A already in cat form (produced by gru/gather): only W conversion + GEMM
static void gemm_precat(const __nv_bfloat16* Acat, const float* W, const float* bias,
                        float* C, int M, int Nreal, int Npad, int K, int ldC)
{
    long tw = (long)Npad * K;
    conv_W<<<(unsigned)((tw + 255) / 256), 256>>>(W, s_Wcat, K, Nreal, tw);
    dim3 grid(Npad / 128, M / 128);
    mma_gemm<<<grid, 256, MMG_SMEM>>>(Acat, s_Wcat, bias, C, 3 * K, Nreal, ldC);
}

extern "C" void kernel_launch(void* const* d_in, const int* in_sizes, int n_in,
                              void* d_out, int out_size)
{
    const float* source    = (const float*)d_in[0];
    const int*   tgt_ids   = (const int*)  d_in[1];
    const int*   lengths   = (const int*)  d_in[2];
    const float* emb       = (const float*)d_in[3];
    const float* eWih0 = (const float*)d_in[4],  *eWhh0 = (const float*)d_in[5];
    const float* ebih0 = (const float*)d_in[6],  *ebhh0 = (const float*)d_in[7];
    const float* eWih1 = (const float*)d_in[8],  *eWhh1 = (const float*)d_in[9];
    const float* ebih1 = (const float*)d_in[10], *ebhh1 = (const float*)d_in[11];
    const float* dWih0 = (const float*)d_in[12], *dWhh0 = (const float*)d_in[13];
    const float* dbih0 = (const float*)d_in[14], *dbhh0 = (const float*)d_in[15];
    const float* dWih1 = (const float*)d_in[16], *dWhh1 = (const float*)d_in[17];
    const float* dbih1 = (const float*)d_in[18], *dbhh1 = (const float*)d_in[19];
    const float* fcW1 = (const float*)d_in[20], *fcb1 = (const float*)d_in[21];
    const float* fcW2 = (const float*)d_in[22], *fcb2 = (const float*)d_in[23];
    const float* fcW3 = (const float*)d_in[24], *fcb3 = (const float*)d_in[25];
    float* out = (float*)d_out;

    float *GI, *Yd1, *hA, *hB, *hC, *hD, *pooled, *F1, *F2, *F3, *rl;
    int* ctr;
    cudaGetSymbolAddress((void**)&GI,  g_GI);
    cudaGetSymbolAddress((void**)&Yd1, g_Yd1);
    cudaGetSymbolAddress((void**)&hA,  g_hA);
    cudaGetSymbolAddress((void**)&hB,  g_hB);
    cudaGetSymbolAddress((void**)&hC,  g_hC);
    cudaGetSymbolAddress((void**)&hD,  g_hD);
    cudaGetSymbolAddress((void**)&pooled, g_pooled);
    cudaGetSymbolAddress((void**)&F1,  g_F1);
    cudaGetSymbolAddress((void**)&F2,  g_F2);
    cudaGetSymbolAddress((void**)&F3,  g_F3);
    cudaGetSymbolAddress((void**)&rl,  g_rowloss);
    cudaGetSymbolAddress((void**)&ctr, g_ctr);
    cudaGetSymbolAddress((void**)&s_Acat, g_Acat);
    cudaGetSymbolAddress((void**)&s_Wcat, g_Wcat);

    cudaFuncSetAttribute(gru_layer_persist,
                         cudaFuncAttributeMaxDynamicSharedMemorySize, SMEM_PERSIST);
    cudaFuncSetAttribute(mma_gemm,
                         cudaFuncAttributeMaxDynamicSharedMemorySize, MMG_SMEM);

    cudaMemsetAsync(hA, 0, 65536 * sizeof(float), 0);
    cudaMemsetAsync(hB, 0, 65536 * sizeof(float), 0);
    cudaMemsetAsync(ctr, 0, 8 * sizeof(int), 0);

    // ---- encoder layer 0: GEMM(source) -> GI; recurrence writes Y0 in cat form ----
    gemm_full(source, eWih0, ebih0, GI, B_ * S_, G3H, G3H, D_, G3H);
    gru_layer_persist<<<128, 256, SMEM_PERSIST>>>(
        GI, (long)S_ * G3H, eWhh0, ebhh0,
        hA, hA, (float*)0, 0, 0, s_Acat /*Y0 cat, row=b*S+t*/, S_, ctr + 0);

    // ---- encoder layer 1 ----
    gemm_precat(s_Acat, eWih1, ebih1, GI, B_ * S_, G3H, G3H, H_, G3H);
    gru_layer_persist<<<128, 256, SMEM_PERSIST>>>(
        GI, (long)S_ * G3H, eWhh1, ebhh1,
        hB, hB, (float*)0, 0, 0, (__nv_bfloat16*)0, S_, ctr + 2);

    // ---- decoder layer 0: embed in cat form; recurrence writes Yd0 cat ----
    gather_emb_cat<<<B_ * T_, 256>>>(tgt_ids, emb, s_Acat);
    gemm_precat(s_Acat, dWih0, dbih0, GI, B_ * T_, G3H, G3H, E_, G3H);
    gru_layer_persist<<<128, 256, SMEM_PERSIST>>>(
        GI, (long)T_ * G3H, dWhh0, dbhh0,
        hA /*enc L0 final*/, hC, (float*)0, 0, 0, s_Acat /*Yd0 cat*/, T_, ctr + 4);

    // ---- decoder layer 1: recurrence writes Yd1 fp32 (for pooling) ----
    gemm_precat(s_Acat, dWih1, dbih1, GI, B_ * T_, G3H, G3H, H_, G3H);
    gru_layer_persist<<<128, 256, SMEM_PERSIST>>>(
        GI, (long)T_ * G3H, dWhh1, dbhh1,
        hB /*enc L1 final*/, hD, Yd1, (long)T_ * H_, (long)H_, (__nv_bfloat16*)0, T_, ctr + 6);

    // ---- pool + FC head + loss ----
    pool_kernel<<<256, 256>>>(Yd1, lengths, pooled);
    gemm_full(pooled, fcW1, fcb1, F1, B_, 5 * H_, 5 * H_, H_,     5 * H_);
    gemm_full(F1,     fcW2, fcb2, F2, B_, 2 * H_, 2 * H_, 5 * H_, 2 * H_);
    gemm_full(F2,     fcW3, fcb3, F3, B_, V_,     1024,   2 * H_, 1024);
    rowloss_kernel<<<B_, 256>>>(F3, rl, 1024);
    finalize_kernel<<<1, 128>>>(rl, out);
}